// round 12
// baseline (speedup 1.0000x reference)
#include <cuda_runtime.h>
#include <math.h>
#include <stdint.h>

#define N_NODES 20000
#define N_EDGES 320000
#define HDIM 128
#define FIN 162

typedef unsigned long long u64;

// ---------------- device scratch (static, no allocation) ----------------
__device__ float g_cf0[N_NODES * HDIM];
__device__ float g_cf1[N_NODES * HDIM];
__device__ float g_P[N_NODES * 2 * HDIM];

__device__ int   g_deg[N_NODES];
__device__ int   g_off[N_NODES];
__device__ int   g_pos[N_NODES];
__device__ int   g_ctr;
__device__ int   g_work[2];
__device__ int   g_toS[N_EDGES];
__device__ float4 g_efS[N_EDGES];

// col-max key slots: 0,1,2 = parent feats per iter; 3 = skip max; 4 = cg max
__device__ unsigned g_keys[5 * 128];

// packed / transposed weights
__device__ float g_WeP0[128 * 4];        // [c][t]
__device__ float g_WeP1[128 * 4];
__device__ float g_WskipT[128 * 128];
__device__ float g_WgeoT[128 * 128];
__device__ float g_W2T[384 * 128];       // second_w transposed [j][c]
__device__ float g_WgT[128 * 128];       // second_geo_w transposed [j][c]

// Wp bf16 hi/lo packed in mma.m16n8k16 B-fragment per-lane order:
//   index = ((s*32 + t)*32 + lane)*2 + r   (s=k-step 0..7, t=n-tile 0..31, r=reg 0..1)
__device__ uint32_t g_Bf[2][2][16384];
// Wop bf16 hi/lo B-fragments: K padded 162->176 (11 k-steps), 16 n-tiles
//   index = ((s*16 + t)*32 + lane)*2 + r
__device__ uint32_t g_Bop[2][11264];

// ---------------- helpers ----------------
__device__ __forceinline__ unsigned fkey(float f) {
    unsigned u = __float_as_uint(f);
    return (u & 0x80000000u) ? ~u : (u | 0x80000000u);
}
__device__ __forceinline__ float fdec(unsigned k) {
    unsigned u = (k & 0x80000000u) ? (k & 0x7fffffffu) : ~k;
    return __uint_as_float(u);
}
__device__ __forceinline__ float leaky(float x) { return fmaxf(x, 0.01f * x); }

__device__ __forceinline__ u64 pack2(float lo, float hi) {
    u64 r; asm("mov.b64 %0, {%1, %2};" : "=l"(r) : "f"(lo), "f"(hi)); return r;
}
__device__ __forceinline__ void unpack2(u64 v, float& lo, float& hi) {
    asm("mov.b64 {%0, %1}, %2;" : "=f"(lo), "=f"(hi) : "l"(v));
}
__device__ __forceinline__ u64 fma2(u64 a, u64 b, u64 c) {
    u64 d; asm("fma.rn.f32x2 %0, %1, %2, %3;" : "=l"(d) : "l"(a), "l"(b), "l"(c)); return d;
}

// bf16 split: x = hi + lo
__device__ __forceinline__ void bsplit(float x, uint32_t& hb, uint32_t& lb) {
    uint32_t u = __float_as_uint(x);
    hb = (u + 0x7FFFu + ((u >> 16) & 1u)) >> 16;
    float hf = __uint_as_float(hb << 16);
    float r = x - hf;
    uint32_t v = __float_as_uint(r);
    lb = (v + 0x7FFFu + ((v >> 16) & 1u)) >> 16;
}
__device__ __forceinline__ void bsplit2(float a, float b, uint32_t& h2, uint32_t& l2) {
    uint32_t ha, la, hb, lb;
    bsplit(a, ha, la); bsplit(b, hb, lb);
    h2 = ha | (hb << 16);
    l2 = la | (lb << 16);
}

__device__ __forceinline__ void mma16816(float* d, const uint32_t* a, uint32_t b0, uint32_t b1) {
    asm volatile(
        "mma.sync.aligned.m16n8k16.row.col.f32.bf16.bf16.f32 "
        "{%0,%1,%2,%3}, {%4,%5,%6,%7}, {%8,%9}, {%0,%1,%2,%3};"
        : "+f"(d[0]), "+f"(d[1]), "+f"(d[2]), "+f"(d[3])
        : "r"(a[0]), "r"(a[1]), "r"(a[2]), "r"(a[3]), "r"(b0), "r"(b1));
}

// ---------------- init (CSR-side state only; runs on csr stream) ----------------
__global__ void k_init() {
    int i = blockIdx.x * 256 + threadIdx.x;
    if (i < N_NODES) g_deg[i] = 0;
    if (i == 0) { g_ctr = 0; g_work[0] = 0; g_work[1] = 0; }
}

// ---------------- weight pack / transpose (+ keys init) ----------------
__global__ void k_prep(const float* __restrict__ wop, const float* __restrict__ ew,
                       const float* __restrict__ wskip, const float* __restrict__ wgeo,
                       const float* __restrict__ w2, const float* __restrict__ wg2) {
    int i = blockIdx.x * 256 + threadIdx.x;
    const int B1 = 2 * 16384;    // Wp fragments
    const int B2 = 11264;        // Wop fragments
    const int C = 2 * 128 * 4;
    const int D = 128 * 128;
    const int E = 128 * 128;
    const int F = 384 * 128;
    const int G = 128 * 128;
    const int H = 5 * 128;
    if (i < B1) {
        int it = i >> 14;
        int r14 = i & 16383;
        int r = r14 & 1;
        int l = (r14 >> 1) & 31;
        int t = (r14 >> 6) & 31;
        int s = r14 >> 11;
        int k = s * 16 + (l & 3) * 2 + r * 8;
        int n = t * 8 + (l >> 2);
        const float* row = (n < 128) ? (ew + (it * 128 + n) * 260)
                                     : (ew + (it * 128 + (n - 128)) * 260 + 128);
        float w0 = row[k], w1 = row[k + 1];
        uint32_t h2, l2; bsplit2(w0, w1, h2, l2);
        g_Bf[it][0][r14] = h2;
        g_Bf[it][1][r14] = l2;
        return;
    }
    i -= B1;
    if (i < B2) {
        int r = i & 1;
        int l = (i >> 1) & 31;
        int st = i >> 6;
        int t = st & 15;
        int s = st >> 4;
        int k = s * 16 + (l & 3) * 2 + r * 8;
        int n = t * 8 + (l >> 2);
        float w0 = (k < FIN)     ? wop[n * FIN + k]     : 0.f;
        float w1 = (k + 1 < FIN) ? wop[n * FIN + k + 1] : 0.f;
        uint32_t h2, l2; bsplit2(w0, w1, h2, l2);
        g_Bop[0][i] = h2;
        g_Bop[1][i] = l2;
        return;
    }
    i -= B2;
    if (i < C) {
        int it = i / (128 * 4); int r = i % (128 * 4);
        (it ? g_WeP1 : g_WeP0)[r] = ew[(it * 128 + r / 4) * 260 + 256 + (r & 3)]; return;
    }
    i -= C;
    if (i < D) { int k = i / 128, c = i % 128; g_WskipT[i] = wskip[c * 128 + k]; return; }
    i -= D;
    if (i < E) { int k = i / 128, c = i % 128; g_WgeoT[i]  = wgeo[c * 128 + k]; return; }
    i -= E;
    if (i < F) { int j = i / 128, c = i % 128; g_W2T[i] = w2[c * 384 + j]; return; }
    i -= F;
    if (i < G) { int j = i / 128, c = i % 128; g_WgT[i] = wg2[c * 128 + j]; return; }
    i -= G;
    if (i < H) g_keys[i] = fkey(-3.402823466e38f);
}

// ---------------- CSR build ----------------
__global__ void k_hist(const int* __restrict__ eidx) {
    int e = blockIdx.x * 256 + threadIdx.x;
    if (e < N_EDGES) atomicAdd(&g_deg[eidx[2 * e]], 1);
}

__global__ void k_assign() {
    __shared__ int wsum[8];
    __shared__ int sbase;
    int i = blockIdx.x * 256 + threadIdx.x;
    int d = (i < N_NODES) ? g_deg[i] : 0;
    int lane = threadIdx.x & 31, w = threadIdx.x >> 5;
    int p = d;
#pragma unroll
    for (int o = 1; o < 32; o <<= 1) {
        int v = __shfl_up_sync(0xffffffffu, p, o);
        if (lane >= o) p += v;
    }
    if (lane == 31) wsum[w] = p;
    __syncthreads();
    if (threadIdx.x == 0) {
        int s = 0;
#pragma unroll
        for (int k = 0; k < 8; k++) { int t = wsum[k]; wsum[k] = s; s += t; }
        sbase = atomicAdd(&g_ctr, s);
    }
    __syncthreads();
    int off = sbase + wsum[w] + p - d;
    if (i < N_NODES) { g_off[i] = off; g_pos[i] = off; }
}

__global__ void k_sort(const int* __restrict__ eidx, const float* __restrict__ etype) {
    int e = blockIdx.x * 256 + threadIdx.x;
    if (e < N_EDGES) {
        int f = eidx[2 * e], to = eidx[2 * e + 1];
        int slot = atomicAdd(&g_pos[f], 1);
        g_toS[slot] = to;
        g_efS[slot] = *(const float4*)(etype + 4 * e);
    }
}

// ---------------- f32x2 GEMM (skip / geo, colmax-only, off critical path) ----------------
enum { WS_SKIP = 3, WS_GEO = 4 };

__device__ __forceinline__ const float* sel_w(int s) {
    return (s == WS_SKIP) ? g_WskipT : g_WgeoT;
}

template<int K, int COUT>
__global__ void __launch_bounds__(256)
k_gemm(const float* __restrict__ Xext, int wsel,
       const float* __restrict__ bias, const float* __restrict__ exists, int slot) {
    constexpr int CH_T = COUT / 8;
    constexpr int ND_T = 256 / CH_T;
    constexpr int TN   = ND_T * 8;
    constexpr int XP   = TN + 2;
    constexpr int NKC  = K / 32;

    __shared__ __align__(16) float sW[32 * COUT];
    __shared__ __align__(16) u64   sX2[32 * XP];
    __shared__ __align__(16) float sRed[ND_T * COUT];

    const float* X  = Xext;
    const float* Wt = sel_w(wsel);

    int tid = threadIdx.x;
    int ct = tid % CH_T, nt = tid / CH_T;
    int nb = blockIdx.x * TN;

    u64* sW64 = reinterpret_cast<u64*>(sW);

    u64 acc2[4][8];
#pragma unroll
    for (int c = 0; c < 4; c++)
#pragma unroll
        for (int n = 0; n < 8; n++) acc2[c][n] = 0ull;

    for (int kc = 0; kc < NKC; kc++) {
        int k0 = kc * 32;
#pragma unroll
        for (int p = 0; p < COUT * 8 / 256; p++) {
            int idx4 = tid + p * 256;
            int c4 = idx4 % (COUT / 4), kk = idx4 / (COUT / 4);
            int k = k0 + kk;
            float4 wv = *(const float4*)(Wt + k * COUT + c4 * 4);
            int c = c4 * 4;
            int ct0 = c >> 3;
            int j0  = (c & 7) >> 1;
            int base = kk * (COUT / 2) + ct0;
            sW64[base + j0 * CH_T]       = pack2(wv.x, wv.y);
            sW64[base + (j0 + 1) * CH_T] = pack2(wv.z, wv.w);
        }
#pragma unroll
        for (int p = 0; p < TN * 8 / 256; p++) {
            int idx4 = tid + p * 256;
            int kq = idx4 & 7, n = idx4 >> 3;
            int node = nb + n;
            float4 xv = make_float4(0.f, 0.f, 0.f, 0.f);
            if (node < N_NODES) xv = *(const float4*)(X + node * K + k0 + kq * 4);
            sX2[(kq * 4 + 0) * XP + n] = pack2(xv.x, xv.x);
            sX2[(kq * 4 + 1) * XP + n] = pack2(xv.y, xv.y);
            sX2[(kq * 4 + 2) * XP + n] = pack2(xv.z, xv.z);
            sX2[(kq * 4 + 3) * XP + n] = pack2(xv.w, xv.w);
        }
        __syncthreads();
#pragma unroll 8
        for (int kk = 0; kk < 32; kk++) {
            int wb = kk * (COUT / 2) + ct;
            u64 w_[4];
#pragma unroll
            for (int j = 0; j < 4; j++) w_[j] = sW64[wb + j * CH_T];
            const ulonglong2* xr = reinterpret_cast<const ulonglong2*>(sX2 + kk * XP + nt * 8);
            ulonglong2 xa = xr[0], xb = xr[1], xc = xr[2], xd = xr[3];
            u64 x_[8] = { xa.x, xa.y, xb.x, xb.y, xc.x, xc.y, xd.x, xd.y };
#pragma unroll
            for (int j = 0; j < 4; j++)
#pragma unroll
                for (int n = 0; n < 8; n++)
                    acc2[j][n] = fma2(w_[j], x_[n], acc2[j][n]);
        }
        __syncthreads();
    }

    float b[8];
#pragma unroll
    for (int c = 0; c < 8; c++) b[c] = bias[ct * 8 + c];
    float lmax[8];
#pragma unroll
    for (int c = 0; c < 8; c++) lmax[c] = -3.402823466e38f;

#pragma unroll
    for (int n = 0; n < 8; n++) {
        int node = nb + nt * 8 + n;
        if (node < N_NODES) {
            float ex = exists[node];
            float y[8];
#pragma unroll
            for (int cp = 0; cp < 4; cp++)
                unpack2(acc2[cp][n], y[2 * cp], y[2 * cp + 1]);
#pragma unroll
            for (int c = 0; c < 8; c++) {
                float v = (y[c] + b[c]) * ex;
                lmax[c] = fmaxf(lmax[c], v);
            }
        }
    }

#pragma unroll
    for (int c = 0; c < 8; c++) sRed[nt * COUT + ct * 8 + c] = lmax[c];
    __syncthreads();
    for (int c = tid; c < COUT; c += 256) {
        float m = sRed[c];
#pragma unroll
        for (int r = 1; r < ND_T; r++) m = fmaxf(m, sRed[r * COUT + c]);
        atomicMax(&g_keys[slot * 128 + c], fkey(m));
    }
}

// ---------------- HMMA op-GEMM: cf0 = (child_feats @ Wop^T + b) * exists, colmax slot 0 ----
// Block 256 thr = 8 warps, each warp 16 rows x 128 cols. K padded 162->176 (11 steps).
__global__ void __launch_bounds__(256)
k_opgemm(const float* __restrict__ X, const float* __restrict__ bias,
         const float* __restrict__ exists) {
    __shared__ unsigned sMax[128];
    int tid = threadIdx.x, w = tid >> 5, lane = tid & 31;
    if (tid < 128) sMax[tid] = fkey(-3.402823466e38f);
    __syncthreads();

    int nb = blockIdx.x * 128 + w * 16;
    int g = lane >> 2, tg = lane & 3;
    int row0 = nb + g, row1 = nb + g + 8;
    bool v0 = row0 < N_NODES, v1 = row1 < N_NODES;
    const float* x0 = X + (v0 ? row0 : 0) * FIN;
    const float* x1 = X + (v1 ? row1 : 0) * FIN;
    const uint32_t* Bh = g_Bop[0] + lane * 2;
    const uint32_t* Bl = g_Bop[1] + lane * 2;

    float acc[16][4];
#pragma unroll
    for (int t = 0; t < 16; t++)
#pragma unroll
        for (int q = 0; q < 4; q++) acc[t][q] = 0.f;

#pragma unroll
    for (int s = 0; s < 11; s++) {
        int kb = s * 16 + tg * 2;
        float2 p00, p01, p10, p11;
        if (s < 10) {
            p00 = *(const float2*)(x0 + kb);
            p01 = *(const float2*)(x0 + kb + 8);
            p10 = *(const float2*)(x1 + kb);
            p11 = *(const float2*)(x1 + kb + 8);
        } else {
            p00 = p10 = make_float2(0.f, 0.f);
            p01 = p11 = make_float2(0.f, 0.f);
            if (kb + 1 < FIN) {
                p00 = *(const float2*)(x0 + kb);
                p10 = *(const float2*)(x1 + kb);
            }
        }
        uint32_t ah[4], al[4];
        bsplit2(p00.x, p00.y, ah[0], al[0]);
        bsplit2(p10.x, p10.y, ah[1], al[1]);
        bsplit2(p01.x, p01.y, ah[2], al[2]);
        bsplit2(p11.x, p11.y, ah[3], al[3]);
        const uint32_t* bhp = Bh + s * 1024;   // 16 tiles * 32 lanes * 2
        const uint32_t* blp = Bl + s * 1024;
#pragma unroll
        for (int t = 0; t < 16; t++) {
            uint2 bh = *(const uint2*)(bhp + t * 64);
            uint2 bl = *(const uint2*)(blp + t * 64);
            mma16816(acc[t], ah, bh.x, bh.y);
            mma16816(acc[t], ah, bl.x, bl.y);
            mma16816(acc[t], al, bh.x, bh.y);
        }
    }

    float ex0 = v0 ? exists[row0] : 0.f;
    float ex1 = v1 ? exists[row1] : 0.f;
    const float NEG = -3.402823466e38f;
#pragma unroll
    for (int t = 0; t < 16; t++) {
        int ch = t * 8 + tg * 2;
        float2 b2 = *(const float2*)(bias + ch);
        float y00 = (acc[t][0] + b2.x) * ex0;
        float y01 = (acc[t][1] + b2.y) * ex0;
        float y10 = (acc[t][2] + b2.x) * ex1;
        float y11 = (acc[t][3] + b2.y) * ex1;
        if (v0) *(float2*)(g_cf0 + row0 * 128 + ch) = make_float2(y00, y01);
        if (v1) *(float2*)(g_cf0 + row1 * 128 + ch) = make_float2(y10, y11);
        float m0 = fmaxf(v0 ? y00 : NEG, v1 ? y10 : NEG);
        float m1 = fmaxf(v0 ? y01 : NEG, v1 ? y11 : NEG);
#pragma unroll
        for (int o = 4; o < 32; o <<= 1) {
            m0 = fmaxf(m0, __shfl_xor_sync(0xffffffffu, m0, o));
            m1 = fmaxf(m1, __shfl_xor_sync(0xffffffffu, m1, o));
        }
        if (lane < 4) {
            atomicMax(&sMax[ch],     fkey(m0));
            atomicMax(&sMax[ch + 1], fkey(m1));
        }
    }
    __syncthreads();
    if (tid < 128) atomicMax(&g_keys[tid], sMax[tid]);
}

// ---------------- mma.sync P-GEMM: P[64 nodes/block, 256] = cf @ Wp^T ----------------
__global__ void __launch_bounds__(256)
k_pgemm(int xsel, int it) {
    const float* X = xsel ? g_cf1 : g_cf0;
    int tid = threadIdx.x, w = tid >> 5, lane = tid & 31;
    int chhalf = w >> 2;
    int nb = blockIdx.x * 64 + (w & 3) * 16;
    int g = lane >> 2;
    int tg = lane & 3;
    int row0 = nb + g, row1 = nb + g + 8;
    bool v0 = row0 < N_NODES, v1 = row1 < N_NODES;
    const float* x0 = X + (v0 ? row0 : 0) * 128;
    const float* x1 = X + (v1 ? row1 : 0) * 128;
    const uint32_t* Bh = g_Bf[it][0] + ((chhalf * 16) * 32 + lane) * 2;
    const uint32_t* Bl = g_Bf[it][1] + ((chhalf * 16) * 32 + lane) * 2;

    float acc[16][4];
#pragma unroll
    for (int t = 0; t < 16; t++)
#pragma unroll
        for (int q = 0; q < 4; q++) acc[t][q] = 0.f;

#pragma unroll
    for (int s = 0; s < 8; s++) {
        int kb = s * 16 + tg * 2;
        float2 p00 = *(const float2*)(x0 + kb);
        float2 p01 = *(const float2*)(x0 + kb + 8);
        float2 p10 = *(const float2*)(x1 + kb);
        float2 p11 = *(const float2*)(x1 + kb + 8);
        uint32_t ah[4], al[4];
        bsplit2(p00.x, p00.y, ah[0], al[0]);
        bsplit2(p10.x, p10.y, ah[1], al[1]);
        bsplit2(p01.x, p01.y, ah[2], al[2]);
        bsplit2(p11.x, p11.y, ah[3], al[3]);
        const uint32_t* bhp = Bh + s * 2048;
        const uint32_t* blp = Bl + s * 2048;
#pragma unroll
        for (int t = 0; t < 16; t++) {
            uint2 bh = *(const uint2*)(bhp + t * 64);
            uint2 bl = *(const uint2*)(blp + t * 64);
            mma16816(acc[t], ah, bh.x, bh.y);
            mma16816(acc[t], ah, bl.x, bl.y);
            mma16816(acc[t], al, bh.x, bh.y);
        }
    }

    int chb = chhalf * 128 + tg * 2;
#pragma unroll
    for (int t = 0; t < 16; t++) {
        int ch = chb + t * 8;
        if (v0) *(float2*)(g_P + row0 * 256 + ch) = make_float2(acc[t][0], acc[t][1]);
        if (v1) *(float2*)(g_P + row1 * 256 + ch) = make_float2(acc[t][2], acc[t][3]);
    }
}

// ---------------- per-node gather + max, load-balanced, 2-edge ILP ----------------
template<bool STORE>
__global__ void __launch_bounds__(512)
k_edge(const float* __restrict__ eb, int wesel, int slot) {
    const float* WeP = wesel ? g_WeP1 : g_WeP0;
    int warp = threadIdx.x >> 5, lane = threadIdx.x & 31;
    __shared__ __align__(16) float sRed[16 * 128];

    const float4* P4 = (const float4*)g_P;
    float4 b4 = *(const float4*)(eb + lane * 4);
    const float4* We4 = (const float4*)WeP;
    float4 we0 = We4[lane * 4 + 0];
    float4 we1 = We4[lane * 4 + 1];
    float4 we2 = We4[lane * 4 + 2];
    float4 we3 = We4[lane * 4 + 3];

    float4 cmax = make_float4(-3.402823466e38f, -3.402823466e38f,
                              -3.402823466e38f, -3.402823466e38f);
    for (;;) {
        int v0i = 0;
        if (lane == 0) v0i = atomicAdd(&g_work[wesel], 2);
        v0i = __shfl_sync(0xffffffffu, v0i, 0);
        if (v0i >= N_NODES) break;
        int vend = (v0i + 2 < N_NODES) ? v0i + 2 : N_NODES;
        for (int v = v0i; v < vend; v++) {
            float4 pa = P4[v * 64 + lane];
            float4 base = { pa.x + b4.x, pa.y + b4.y, pa.z + b4.z, pa.w + b4.w };
            int start = g_off[v], deg = g_deg[v];
            float4 acc = make_float4(0.f, 0.f, 0.f, 0.f);
            int j = 0;
            for (; j + 2 <= deg; j += 2) {
                int toA = g_toS[start + j];
                int toB = g_toS[start + j + 1];
                float4 efA = g_efS[start + j];
                float4 efB = g_efS[start + j + 1];
                float4 pbA = P4[toA * 64 + 32 + lane];
                float4 pbB = P4[toB * 64 + 32 + lane];
                float a0 = fmaf(we0.x, efA.x, fmaf(we0.y, efA.y, fmaf(we0.z, efA.z, we0.w * efA.w)));
                float a1 = fmaf(we1.x, efA.x, fmaf(we1.y, efA.y, fmaf(we1.z, efA.z, we1.w * efA.w)));
                float a2 = fmaf(we2.x, efA.x, fmaf(we2.y, efA.y, fmaf(we2.z, efA.z, we2.w * efA.w)));
                float a3 = fmaf(we3.x, efA.x, fmaf(we3.y, efA.y, fmaf(we3.z, efA.z, we3.w * efA.w)));
                float c0 = fmaf(we0.x, efB.x, fmaf(we0.y, efB.y, fmaf(we0.z, efB.z, we0.w * efB.w)));
                float c1 = fmaf(we1.x, efB.x, fmaf(we1.y, efB.y, fmaf(we1.z, efB.z, we1.w * efB.w)));
                float c2 = fmaf(we2.x, efB.x, fmaf(we2.y, efB.y, fmaf(we2.z, efB.z, we2.w * efB.w)));
                float c3 = fmaf(we3.x, efB.x, fmaf(we3.y, efB.y, fmaf(we3.z, efB.z, we3.w * efB.w)));
                float u0 = base.x + pbA.x + a0, w0_ = base.x + pbB.x + c0;
                float u1 = base.y + pbA.y + a1, w1_ = base.y + pbB.y + c1;
                float u2 = base.z + pbA.z + a2, w2_ = base.z + pbB.z + c2;
                float u3 = base.w + pbA.w + a3, w3_ = base.w + pbB.w + c3;
                acc.x = fmaxf(acc.x, fmaxf(fmaxf(u0, 0.01f * u0), fmaxf(w0_, 0.01f * w0_)));
                acc.y = fmaxf(acc.y, fmaxf(fmaxf(u1, 0.01f * u1), fmaxf(w1_, 0.01f * w1_)));
                acc.z = fmaxf(acc.z, fmaxf(fmaxf(u2, 0.01f * u2), fmaxf(w2_, 0.01f * w2_)));
                acc.w = fmaxf(acc.w, fmaxf(fmaxf(u3, 0.01f * u3), fmaxf(w3_, 0.01f * w3_)));
            }
            if (j < deg) {
                int to = g_toS[start + j];
                float4 ef = g_efS[start + j];
                float4 pb = P4[to * 64 + 32 + lane];
                float d0 = fmaf(we0.x, ef.x, fmaf(we0.y, ef.y, fmaf(we0.z, ef.z, we0.w * ef.w)));
                float d1 = fmaf(we1.x, ef.x, fmaf(we1.y, ef.y, fmaf(we1.z, ef.z, we1.w * ef.w)));
                float d2 = fmaf(we2.x, ef.x, fmaf(we2.y, ef.y, fmaf(we2.z, ef.z, we2.w * ef.w)));
                float d3 = fmaf(we3.x, ef.x, fmaf(we3.y, ef.y, fmaf(we3.z, ef.z, we3.w * ef.w)));
                float u0 = base.x + pb.x + d0;
                float u1 = base.y + pb.y + d1;
                float u2 = base.z + pb.z + d2;
                float u3 = base.w + pb.w + d3;
                acc.x = fmaxf(acc.x, fmaxf(u0, 0.01f * u0));
                acc.y = fmaxf(acc.y, fmaxf(u1, 0.01f * u1));
                acc.z = fmaxf(acc.z, fmaxf(u2, 0.01f * u2));
                acc.w = fmaxf(acc.w, fmaxf(u3, 0.01f * u3));
            }
            if (STORE) *(float4*)(g_cf1 + v * 128 + lane * 4) = acc;
            cmax.x = fmaxf(cmax.x, acc.x);
            cmax.y = fmaxf(cmax.y, acc.y);
            cmax.z = fmaxf(cmax.z, acc.z);
            cmax.w = fmaxf(cmax.w, acc.w);
        }
    }
    *(float4*)(sRed + warp * 128 + lane * 4) = cmax;
    __syncthreads();
    int t = threadIdx.x;
    if (t < 128) {
        float m = sRed[t];
#pragma unroll
        for (int r = 1; r < 16; r++) m = fmaxf(m, sRed[r * 128 + t]);
        atomicMax(&g_keys[slot * 128 + t], fkey(m));
    }
}

// ---------------- finalize: tiny GEMMs + group norm ----------------
__global__ void __launch_bounds__(384)
k_final(const float* __restrict__ second_b, const float* __restrict__ sgeo_b,
        const float* __restrict__ gnw, const float* __restrict__ gnb,
        float* __restrict__ out) {
    __shared__ float spf[384];
    __shared__ float spg[128];
    int t = threadIdx.x;
    if (t < 384) spf[t] = fdec(g_keys[t]);
    if (t < 128) spg[t] = leaky(fdec(g_keys[512 + t]));
    __syncthreads();
    if (t < 128) {
        float a = 0.f;
#pragma unroll 4
        for (int j = 0; j < 384; j++) a = fmaf(spf[j], g_W2T[j * 128 + t], a);
        a += second_b[t];
        out[t] = leaky(a);

        float g = 0.f;
#pragma unroll 4
        for (int j = 0; j < 128; j++) g = fmaf(spg[j], g_WgT[j * 128 + t], g);
        g += sgeo_b[t];

        float s = g;
        s += __shfl_xor_sync(0xffffffffu, s, 1, 8);
        s += __shfl_xor_sync(0xffffffffu, s, 2, 8);
        s += __shfl_xor_sync(0xffffffffu, s, 4, 8);
        float mu = s * 0.125f;
        float d = g - mu;
        float q = d * d;
        q += __shfl_xor_sync(0xffffffffu, q, 1, 8);
        q += __shfl_xor_sync(0xffffffffu, q, 2, 8);
        q += __shfl_xor_sync(0xffffffffu, q, 4, 8);
        float var = q * 0.125f;
        float xn = d * rsqrtf(var + 1e-5f);
        float y = xn * gnw[t] + gnb[t];
        float sgv = fdec(g_keys[384 + t]);
        float o = leaky(sgv) + y;
        out[128 + t] = leaky(o);
    }
}

// ---------------- host launcher ----------------
static cudaStream_t s_csr = 0, s_geo = 0;
static cudaEvent_t evFork = 0, evPrep = 0, evCsr = 0, evGeo = 0;

extern "C" void kernel_launch(void* const* d_in, const int* in_sizes, int n_in,
                              void* d_out, int out_size) {
    const float* child_feats = (const float*)d_in[0];
    const float* child_geo   = (const float*)d_in[1];
    const float* exists      = (const float*)d_in[2];
    const float* etype       = (const float*)d_in[3];
    const int*   eidx        = (const int*)d_in[4];
    const float* wop   = (const float*)d_in[5];
    const float* bop   = (const float*)d_in[6];
    const float* w2    = (const float*)d_in[7];
    const float* b2    = (const float*)d_in[8];
    const float* ew    = (const float*)d_in[9];
    const float* ebias = (const float*)d_in[10];
    const float* wgeo  = (const float*)d_in[11];
    const float* bgeo  = (const float*)d_in[12];
    const float* wg2   = (const float*)d_in[13];
    const float* bg2   = (const float*)d_in[14];
    const float* gnw   = (const float*)d_in[15];
    const float* gnb   = (const float*)d_in[16];
    const float* wskip = (const float*)d_in[17];
    const float* bskip = (const float*)d_in[18];
    float* out = (float*)d_out;

    (void)in_sizes; (void)n_in; (void)out_size;

    if (!s_csr) {
        cudaStreamCreateWithFlags(&s_csr, cudaStreamNonBlocking);
        cudaStreamCreateWithFlags(&s_geo, cudaStreamNonBlocking);
        cudaEventCreateWithFlags(&evFork, cudaEventDisableTiming);
        cudaEventCreateWithFlags(&evPrep, cudaEventDisableTiming);
        cudaEventCreateWithFlags(&evCsr,  cudaEventDisableTiming);
        cudaEventCreateWithFlags(&evGeo,  cudaEventDisableTiming);
    }

    // fork side streams from the capture-origin stream (required for graph capture)
    cudaEventRecord(evFork, 0);
    cudaStreamWaitEvent(s_csr, evFork, 0);
    cudaStreamWaitEvent(s_geo, evFork, 0);

    // CSR stream: independent of weight prep
    k_init<<<(N_NODES + 255) / 256, 256, 0, s_csr>>>();
    k_hist<<<(N_EDGES + 255) / 256, 256, 0, s_csr>>>(eidx);
    k_assign<<<(N_NODES + 255) / 256, 256, 0, s_csr>>>();
    k_sort<<<(N_EDGES + 255) / 256, 256, 0, s_csr>>>(eidx, etype);
    cudaEventRecord(evCsr, s_csr);

    // main stream: weight packing (incl. g_keys init)
    {
        const int total = 2 * 16384 + 11264 + 2 * 128 * 4
                        + 128 * 128 + 128 * 128 + 384 * 128 + 128 * 128 + 5 * 128;
        k_prep<<<(total + 255) / 256, 256>>>(wop, ew, wskip, wgeo, w2, wg2);
    }
    cudaEventRecord(evPrep, 0);

    // geo stream (needs packed weights + keys init)
    cudaStreamWaitEvent(s_geo, evPrep, 0);
    k_gemm<128, 128><<<(N_NODES + 127) / 128, 256, 0, s_geo>>>(
        child_geo, WS_SKIP, bskip, exists, 3);
    k_gemm<128, 128><<<(N_NODES + 127) / 128, 256, 0, s_geo>>>(
        child_geo, WS_GEO, bgeo, exists, 4);
    cudaEventRecord(evGeo, s_geo);

    // main chain: op GEMM on HMMA
    k_opgemm<<<(N_NODES + 127) / 128, 256>>>(child_feats, bop, exists);

    // iteration 0
    k_pgemm<<<(N_NODES + 63) / 64, 256>>>(0, 0);
    cudaStreamWaitEvent(0, evCsr, 0);
    k_edge<true><<<296, 512>>>(ebias, 0, 1);

    // iteration 1
    k_pgemm<<<(N_NODES + 63) / 64, 256>>>(1, 1);
    k_edge<false><<<296, 512>>>(ebias + 128, 1, 2);

    // finalize
    cudaStreamWaitEvent(0, evGeo, 0);
    k_final<<<1, 384>>>(b2, bg2, gnw, gnb, out);
}

// round 13
// speedup vs baseline: 1.0364x; 1.0364x over previous
#include <cuda_runtime.h>
#include <math.h>
#include <stdint.h>

#define N_NODES 20000
#define N_EDGES 320000
#define HDIM 128
#define FIN 162

typedef unsigned long long u64;

// ---------------- device scratch (static, no allocation) ----------------
__device__ float g_cf0[N_NODES * HDIM];
__device__ float g_cf1[N_NODES * HDIM];
__device__ float g_P[N_NODES * 2 * HDIM];

__device__ int   g_deg[N_NODES];
__device__ int   g_off[N_NODES];
__device__ int   g_pos[N_NODES];
__device__ int   g_ctr;
__device__ int   g_work[2];
__device__ int   g_toS[N_EDGES];
__device__ float4 g_efS[N_EDGES];

// col-max key slots: 0,1,2 = parent feats per iter; 3 = skip max; 4 = cg max
__device__ unsigned g_keys[5 * 128];

// packed / transposed weights
__device__ float g_WeP0[128 * 4];        // [c][t]
__device__ float g_WeP1[128 * 4];
__device__ float g_WskipT[128 * 128];
__device__ float g_WgeoT[128 * 128];
__device__ float g_W2T[384 * 128];       // second_w transposed [j][c]
__device__ float g_WgT[128 * 128];       // second_geo_w transposed [j][c]

// Wp bf16 hi/lo packed in mma.m16n8k16 B-fragment per-lane order:
//   index = ((s*32 + t)*32 + lane)*2 + r   (s=k-step 0..7, t=n-tile 0..31, r=reg 0..1)
__device__ uint32_t g_Bf[2][2][16384];
// Wop bf16 hi/lo B-fragments: K padded 162->176 (11 k-steps), 16 n-tiles
//   index = ((s*16 + t)*32 + lane)*2 + r
__device__ uint32_t g_Bop[2][11264];

// ---------------- helpers ----------------
__device__ __forceinline__ unsigned fkey(float f) {
    unsigned u = __float_as_uint(f);
    return (u & 0x80000000u) ? ~u : (u | 0x80000000u);
}
__device__ __forceinline__ float fdec(unsigned k) {
    unsigned u = (k & 0x80000000u) ? (k & 0x7fffffffu) : ~k;
    return __uint_as_float(u);
}
__device__ __forceinline__ float leaky(float x) { return fmaxf(x, 0.01f * x); }

__device__ __forceinline__ u64 pack2(float lo, float hi) {
    u64 r; asm("mov.b64 %0, {%1, %2};" : "=l"(r) : "f"(lo), "f"(hi)); return r;
}
__device__ __forceinline__ void unpack2(u64 v, float& lo, float& hi) {
    asm("mov.b64 {%0, %1}, %2;" : "=f"(lo), "=f"(hi) : "l"(v));
}
__device__ __forceinline__ u64 fma2(u64 a, u64 b, u64 c) {
    u64 d; asm("fma.rn.f32x2 %0, %1, %2, %3;" : "=l"(d) : "l"(a), "l"(b), "l"(c)); return d;
}

// bf16 split: x = hi + lo
__device__ __forceinline__ void bsplit(float x, uint32_t& hb, uint32_t& lb) {
    uint32_t u = __float_as_uint(x);
    hb = (u + 0x7FFFu + ((u >> 16) & 1u)) >> 16;
    float hf = __uint_as_float(hb << 16);
    float r = x - hf;
    uint32_t v = __float_as_uint(r);
    lb = (v + 0x7FFFu + ((v >> 16) & 1u)) >> 16;
}
__device__ __forceinline__ void bsplit2(float a, float b, uint32_t& h2, uint32_t& l2) {
    uint32_t ha, la, hb, lb;
    bsplit(a, ha, la); bsplit(b, hb, lb);
    h2 = ha | (hb << 16);
    l2 = la | (lb << 16);
}

__device__ __forceinline__ void mma16816(float* d, const uint32_t* a, uint32_t b0, uint32_t b1) {
    asm volatile(
        "mma.sync.aligned.m16n8k16.row.col.f32.bf16.bf16.f32 "
        "{%0,%1,%2,%3}, {%4,%5,%6,%7}, {%8,%9}, {%0,%1,%2,%3};"
        : "+f"(d[0]), "+f"(d[1]), "+f"(d[2]), "+f"(d[3])
        : "r"(a[0]), "r"(a[1]), "r"(a[2]), "r"(a[3]), "r"(b0), "r"(b1));
}

// ---------------- init (CSR-side state only; runs on csr stream) ----------------
__global__ void k_init() {
    int i = blockIdx.x * 256 + threadIdx.x;
    if (i < N_NODES) g_deg[i] = 0;
    if (i == 0) { g_ctr = 0; g_work[0] = 0; g_work[1] = 0; }
}

// ---------------- weight pack / transpose (+ keys init) ----------------
__global__ void k_prep(const float* __restrict__ wop, const float* __restrict__ ew,
                       const float* __restrict__ wskip, const float* __restrict__ wgeo,
                       const float* __restrict__ w2, const float* __restrict__ wg2) {
    int i = blockIdx.x * 256 + threadIdx.x;
    const int B1 = 2 * 16384;    // Wp fragments
    const int B2 = 11264;        // Wop fragments
    const int C = 2 * 128 * 4;
    const int D = 128 * 128;
    const int E = 128 * 128;
    const int F = 384 * 128;
    const int G = 128 * 128;
    const int H = 5 * 128;
    if (i < B1) {
        int it = i >> 14;
        int r14 = i & 16383;
        int r = r14 & 1;
        int l = (r14 >> 1) & 31;
        int t = (r14 >> 6) & 31;
        int s = r14 >> 11;
        int k = s * 16 + (l & 3) * 2 + r * 8;
        int n = t * 8 + (l >> 2);
        const float* row = (n < 128) ? (ew + (it * 128 + n) * 260)
                                     : (ew + (it * 128 + (n - 128)) * 260 + 128);
        float w0 = row[k], w1 = row[k + 1];
        uint32_t h2, l2; bsplit2(w0, w1, h2, l2);
        g_Bf[it][0][r14] = h2;
        g_Bf[it][1][r14] = l2;
        return;
    }
    i -= B1;
    if (i < B2) {
        int r = i & 1;
        int l = (i >> 1) & 31;
        int st = i >> 6;
        int t = st & 15;
        int s = st >> 4;
        int k = s * 16 + (l & 3) * 2 + r * 8;
        int n = t * 8 + (l >> 2);
        float w0 = (k < FIN)     ? wop[n * FIN + k]     : 0.f;
        float w1 = (k + 1 < FIN) ? wop[n * FIN + k + 1] : 0.f;
        uint32_t h2, l2; bsplit2(w0, w1, h2, l2);
        g_Bop[0][i] = h2;
        g_Bop[1][i] = l2;
        return;
    }
    i -= B2;
    if (i < C) {
        int it = i / (128 * 4); int r = i % (128 * 4);
        (it ? g_WeP1 : g_WeP0)[r] = ew[(it * 128 + r / 4) * 260 + 256 + (r & 3)]; return;
    }
    i -= C;
    if (i < D) { int k = i / 128, c = i % 128; g_WskipT[i] = wskip[c * 128 + k]; return; }
    i -= D;
    if (i < E) { int k = i / 128, c = i % 128; g_WgeoT[i]  = wgeo[c * 128 + k]; return; }
    i -= E;
    if (i < F) { int j = i / 128, c = i % 128; g_W2T[i] = w2[c * 384 + j]; return; }
    i -= F;
    if (i < G) { int j = i / 128, c = i % 128; g_WgT[i] = wg2[c * 128 + j]; return; }
    i -= G;
    if (i < H) g_keys[i] = fkey(-3.402823466e38f);
}

// ---------------- CSR build ----------------
__global__ void k_hist(const int* __restrict__ eidx) {
    int e = blockIdx.x * 256 + threadIdx.x;
    if (e < N_EDGES) atomicAdd(&g_deg[eidx[2 * e]], 1);
}

__global__ void k_assign() {
    __shared__ int wsum[8];
    __shared__ int sbase;
    int i = blockIdx.x * 256 + threadIdx.x;
    int d = (i < N_NODES) ? g_deg[i] : 0;
    int lane = threadIdx.x & 31, w = threadIdx.x >> 5;
    int p = d;
#pragma unroll
    for (int o = 1; o < 32; o <<= 1) {
        int v = __shfl_up_sync(0xffffffffu, p, o);
        if (lane >= o) p += v;
    }
    if (lane == 31) wsum[w] = p;
    __syncthreads();
    if (threadIdx.x == 0) {
        int s = 0;
#pragma unroll
        for (int k = 0; k < 8; k++) { int t = wsum[k]; wsum[k] = s; s += t; }
        sbase = atomicAdd(&g_ctr, s);
    }
    __syncthreads();
    int off = sbase + wsum[w] + p - d;
    if (i < N_NODES) { g_off[i] = off; g_pos[i] = off; }
}

__global__ void k_sort(const int* __restrict__ eidx, const float* __restrict__ etype) {
    int e = blockIdx.x * 256 + threadIdx.x;
    if (e < N_EDGES) {
        int f = eidx[2 * e], to = eidx[2 * e + 1];
        int slot = atomicAdd(&g_pos[f], 1);
        g_toS[slot] = to;
        g_efS[slot] = *(const float4*)(etype + 4 * e);
    }
}

// ---------------- f32x2 GEMM (skip / geo, colmax-only, off critical path) ----------------
enum { WS_SKIP = 3, WS_GEO = 4 };

__device__ __forceinline__ const float* sel_w(int s) {
    return (s == WS_SKIP) ? g_WskipT : g_WgeoT;
}

template<int K, int COUT>
__global__ void __launch_bounds__(256)
k_gemm(const float* __restrict__ Xext, int wsel,
       const float* __restrict__ bias, const float* __restrict__ exists, int slot) {
    constexpr int CH_T = COUT / 8;
    constexpr int ND_T = 256 / CH_T;
    constexpr int TN   = ND_T * 8;
    constexpr int XP   = TN + 2;
    constexpr int NKC  = K / 32;

    __shared__ __align__(16) float sW[32 * COUT];
    __shared__ __align__(16) u64   sX2[32 * XP];
    __shared__ __align__(16) float sRed[ND_T * COUT];

    const float* X  = Xext;
    const float* Wt = sel_w(wsel);

    int tid = threadIdx.x;
    int ct = tid % CH_T, nt = tid / CH_T;
    int nb = blockIdx.x * TN;

    u64* sW64 = reinterpret_cast<u64*>(sW);

    u64 acc2[4][8];
#pragma unroll
    for (int c = 0; c < 4; c++)
#pragma unroll
        for (int n = 0; n < 8; n++) acc2[c][n] = 0ull;

    for (int kc = 0; kc < NKC; kc++) {
        int k0 = kc * 32;
#pragma unroll
        for (int p = 0; p < COUT * 8 / 256; p++) {
            int idx4 = tid + p * 256;
            int c4 = idx4 % (COUT / 4), kk = idx4 / (COUT / 4);
            int k = k0 + kk;
            float4 wv = *(const float4*)(Wt + k * COUT + c4 * 4);
            int c = c4 * 4;
            int ct0 = c >> 3;
            int j0  = (c & 7) >> 1;
            int base = kk * (COUT / 2) + ct0;
            sW64[base + j0 * CH_T]       = pack2(wv.x, wv.y);
            sW64[base + (j0 + 1) * CH_T] = pack2(wv.z, wv.w);
        }
#pragma unroll
        for (int p = 0; p < TN * 8 / 256; p++) {
            int idx4 = tid + p * 256;
            int kq = idx4 & 7, n = idx4 >> 3;
            int node = nb + n;
            float4 xv = make_float4(0.f, 0.f, 0.f, 0.f);
            if (node < N_NODES) xv = *(const float4*)(X + node * K + k0 + kq * 4);
            sX2[(kq * 4 + 0) * XP + n] = pack2(xv.x, xv.x);
            sX2[(kq * 4 + 1) * XP + n] = pack2(xv.y, xv.y);
            sX2[(kq * 4 + 2) * XP + n] = pack2(xv.z, xv.z);
            sX2[(kq * 4 + 3) * XP + n] = pack2(xv.w, xv.w);
        }
        __syncthreads();
#pragma unroll 8
        for (int kk = 0; kk < 32; kk++) {
            int wb = kk * (COUT / 2) + ct;
            u64 w_[4];
#pragma unroll
            for (int j = 0; j < 4; j++) w_[j] = sW64[wb + j * CH_T];
            const ulonglong2* xr = reinterpret_cast<const ulonglong2*>(sX2 + kk * XP + nt * 8);
            ulonglong2 xa = xr[0], xb = xr[1], xc = xr[2], xd = xr[3];
            u64 x_[8] = { xa.x, xa.y, xb.x, xb.y, xc.x, xc.y, xd.x, xd.y };
#pragma unroll
            for (int j = 0; j < 4; j++)
#pragma unroll
                for (int n = 0; n < 8; n++)
                    acc2[j][n] = fma2(w_[j], x_[n], acc2[j][n]);
        }
        __syncthreads();
    }

    float b[8];
#pragma unroll
    for (int c = 0; c < 8; c++) b[c] = bias[ct * 8 + c];
    float lmax[8];
#pragma unroll
    for (int c = 0; c < 8; c++) lmax[c] = -3.402823466e38f;

#pragma unroll
    for (int n = 0; n < 8; n++) {
        int node = nb + nt * 8 + n;
        if (node < N_NODES) {
            float ex = exists[node];
            float y[8];
#pragma unroll
            for (int cp = 0; cp < 4; cp++)
                unpack2(acc2[cp][n], y[2 * cp], y[2 * cp + 1]);
#pragma unroll
            for (int c = 0; c < 8; c++) {
                float v = (y[c] + b[c]) * ex;
                lmax[c] = fmaxf(lmax[c], v);
            }
        }
    }

#pragma unroll
    for (int c = 0; c < 8; c++) sRed[nt * COUT + ct * 8 + c] = lmax[c];
    __syncthreads();
    for (int c = tid; c < COUT; c += 256) {
        float m = sRed[c];
#pragma unroll
        for (int r = 1; r < ND_T; r++) m = fmaxf(m, sRed[r * COUT + c]);
        atomicMax(&g_keys[slot * 128 + c], fkey(m));
    }
}

// ---------------- HMMA op-GEMM: cf0 = (child_feats @ Wop^T + b) * exists, colmax slot 0 ----
__global__ void __launch_bounds__(256)
k_opgemm(const float* __restrict__ X, const float* __restrict__ bias,
         const float* __restrict__ exists) {
    __shared__ unsigned sMax[128];
    int tid = threadIdx.x, w = tid >> 5, lane = tid & 31;
    if (tid < 128) sMax[tid] = fkey(-3.402823466e38f);
    __syncthreads();

    int nb = blockIdx.x * 128 + w * 16;
    int g = lane >> 2, tg = lane & 3;
    int row0 = nb + g, row1 = nb + g + 8;
    bool v0 = row0 < N_NODES, v1 = row1 < N_NODES;
    const float* x0 = X + (v0 ? row0 : 0) * FIN;
    const float* x1 = X + (v1 ? row1 : 0) * FIN;
    const uint32_t* Bh = g_Bop[0] + lane * 2;
    const uint32_t* Bl = g_Bop[1] + lane * 2;

    float acc[16][4];
#pragma unroll
    for (int t = 0; t < 16; t++)
#pragma unroll
        for (int q = 0; q < 4; q++) acc[t][q] = 0.f;

#pragma unroll
    for (int s = 0; s < 11; s++) {
        int kb = s * 16 + tg * 2;
        float2 p00, p01, p10, p11;
        if (s < 10) {
            p00 = *(const float2*)(x0 + kb);
            p01 = *(const float2*)(x0 + kb + 8);
            p10 = *(const float2*)(x1 + kb);
            p11 = *(const float2*)(x1 + kb + 8);
        } else {
            p00 = p10 = make_float2(0.f, 0.f);
            p01 = p11 = make_float2(0.f, 0.f);
            if (kb + 1 < FIN) {
                p00 = *(const float2*)(x0 + kb);
                p10 = *(const float2*)(x1 + kb);
            }
        }
        uint32_t ah[4], al[4];
        bsplit2(p00.x, p00.y, ah[0], al[0]);
        bsplit2(p10.x, p10.y, ah[1], al[1]);
        bsplit2(p01.x, p01.y, ah[2], al[2]);
        bsplit2(p11.x, p11.y, ah[3], al[3]);
        const uint32_t* bhp = Bh + s * 1024;
        const uint32_t* blp = Bl + s * 1024;
#pragma unroll
        for (int t = 0; t < 16; t++) {
            uint2 bh = *(const uint2*)(bhp + t * 64);
            uint2 bl = *(const uint2*)(blp + t * 64);
            mma16816(acc[t], ah, bh.x, bh.y);
            mma16816(acc[t], ah, bl.x, bl.y);
            mma16816(acc[t], al, bh.x, bh.y);
        }
    }

    float ex0 = v0 ? exists[row0] : 0.f;
    float ex1 = v1 ? exists[row1] : 0.f;
    const float NEG = -3.402823466e38f;
#pragma unroll
    for (int t = 0; t < 16; t++) {
        int ch = t * 8 + tg * 2;
        float2 b2 = *(const float2*)(bias + ch);
        float y00 = (acc[t][0] + b2.x) * ex0;
        float y01 = (acc[t][1] + b2.y) * ex0;
        float y10 = (acc[t][2] + b2.x) * ex1;
        float y11 = (acc[t][3] + b2.y) * ex1;
        if (v0) *(float2*)(g_cf0 + row0 * 128 + ch) = make_float2(y00, y01);
        if (v1) *(float2*)(g_cf0 + row1 * 128 + ch) = make_float2(y10, y11);
        float m0 = fmaxf(v0 ? y00 : NEG, v1 ? y10 : NEG);
        float m1 = fmaxf(v0 ? y01 : NEG, v1 ? y11 : NEG);
#pragma unroll
        for (int o = 4; o < 32; o <<= 1) {
            m0 = fmaxf(m0, __shfl_xor_sync(0xffffffffu, m0, o));
            m1 = fmaxf(m1, __shfl_xor_sync(0xffffffffu, m1, o));
        }
        if (lane < 4) {
            atomicMax(&sMax[ch],     fkey(m0));
            atomicMax(&sMax[ch + 1], fkey(m1));
        }
    }
    __syncthreads();
    if (tid < 128) atomicMax(&g_keys[tid], sMax[tid]);
}

// ---------------- mma.sync P-GEMM: P[64 nodes/block, 256] = cf @ Wp^T ----------------
__global__ void __launch_bounds__(256)
k_pgemm(int xsel, int it) {
    const float* X = xsel ? g_cf1 : g_cf0;
    int tid = threadIdx.x, w = tid >> 5, lane = tid & 31;
    int chhalf = w >> 2;
    int nb = blockIdx.x * 64 + (w & 3) * 16;
    int g = lane >> 2;
    int tg = lane & 3;
    int row0 = nb + g, row1 = nb + g + 8;
    bool v0 = row0 < N_NODES, v1 = row1 < N_NODES;
    const float* x0 = X + (v0 ? row0 : 0) * 128;
    const float* x1 = X + (v1 ? row1 : 0) * 128;
    const uint32_t* Bh = g_Bf[it][0] + ((chhalf * 16) * 32 + lane) * 2;
    const uint32_t* Bl = g_Bf[it][1] + ((chhalf * 16) * 32 + lane) * 2;

    float acc[16][4];
#pragma unroll
    for (int t = 0; t < 16; t++)
#pragma unroll
        for (int q = 0; q < 4; q++) acc[t][q] = 0.f;

#pragma unroll
    for (int s = 0; s < 8; s++) {
        int kb = s * 16 + tg * 2;
        float2 p00 = *(const float2*)(x0 + kb);
        float2 p01 = *(const float2*)(x0 + kb + 8);
        float2 p10 = *(const float2*)(x1 + kb);
        float2 p11 = *(const float2*)(x1 + kb + 8);
        uint32_t ah[4], al[4];
        bsplit2(p00.x, p00.y, ah[0], al[0]);
        bsplit2(p10.x, p10.y, ah[1], al[1]);
        bsplit2(p01.x, p01.y, ah[2], al[2]);
        bsplit2(p11.x, p11.y, ah[3], al[3]);
        const uint32_t* bhp = Bh + s * 2048;
        const uint32_t* blp = Bl + s * 2048;
#pragma unroll
        for (int t = 0; t < 16; t++) {
            uint2 bh = *(const uint2*)(bhp + t * 64);
            uint2 bl = *(const uint2*)(blp + t * 64);
            mma16816(acc[t], ah, bh.x, bh.y);
            mma16816(acc[t], ah, bl.x, bl.y);
            mma16816(acc[t], al, bh.x, bh.y);
        }
    }

    int chb = chhalf * 128 + tg * 2;
#pragma unroll
    for (int t = 0; t < 16; t++) {
        int ch = chb + t * 8;
        if (v0) *(float2*)(g_P + row0 * 256 + ch) = make_float2(acc[t][0], acc[t][1]);
        if (v1) *(float2*)(g_P + row1 * 256 + ch) = make_float2(acc[t][2], acc[t][3]);
    }
}

// ---------------- per-node gather + max, dynamically load-balanced (single-edge loop) ----
template<bool STORE>
__global__ void __launch_bounds__(512)
k_edge(const float* __restrict__ eb, int wesel, int slot) {
    const float* WeP = wesel ? g_WeP1 : g_WeP0;
    int warp = threadIdx.x >> 5, lane = threadIdx.x & 31;
    __shared__ __align__(16) float sRed[16 * 128];

    const float4* P4 = (const float4*)g_P;
    float4 b4 = *(const float4*)(eb + lane * 4);
    const float4* We4 = (const float4*)WeP;
    float4 we0 = We4[lane * 4 + 0];
    float4 we1 = We4[lane * 4 + 1];
    float4 we2 = We4[lane * 4 + 2];
    float4 we3 = We4[lane * 4 + 3];

    float4 cmax = make_float4(-3.402823466e38f, -3.402823466e38f,
                              -3.402823466e38f, -3.402823466e38f);
    for (;;) {
        int v0 = 0;
        if (lane == 0) v0 = atomicAdd(&g_work[wesel], 2);
        v0 = __shfl_sync(0xffffffffu, v0, 0);
        if (v0 >= N_NODES) break;
        int vend = (v0 + 2 < N_NODES) ? v0 + 2 : N_NODES;
        for (int v = v0; v < vend; v++) {
            float4 pa = P4[v * 64 + lane];
            float4 base = { pa.x + b4.x, pa.y + b4.y, pa.z + b4.z, pa.w + b4.w };
            int start = g_off[v], deg = g_deg[v];
            float4 acc = make_float4(0.f, 0.f, 0.f, 0.f);
#pragma unroll 4
            for (int j = 0; j < deg; j++) {
                int to = g_toS[start + j];
                float4 ef = g_efS[start + j];
                float4 pb = P4[to * 64 + 32 + lane];
                float d0 = fmaf(we0.x, ef.x, fmaf(we0.y, ef.y, fmaf(we0.z, ef.z, we0.w * ef.w)));
                float d1 = fmaf(we1.x, ef.x, fmaf(we1.y, ef.y, fmaf(we1.z, ef.z, we1.w * ef.w)));
                float d2 = fmaf(we2.x, ef.x, fmaf(we2.y, ef.y, fmaf(we2.z, ef.z, we2.w * ef.w)));
                float d3 = fmaf(we3.x, ef.x, fmaf(we3.y, ef.y, fmaf(we3.z, ef.z, we3.w * ef.w)));
                float v0f = base.x + pb.x + d0;
                float v1f = base.y + pb.y + d1;
                float v2f = base.z + pb.z + d2;
                float v3f = base.w + pb.w + d3;
                acc.x = fmaxf(acc.x, fmaxf(v0f, 0.01f * v0f));
                acc.y = fmaxf(acc.y, fmaxf(v1f, 0.01f * v1f));
                acc.z = fmaxf(acc.z, fmaxf(v2f, 0.01f * v2f));
                acc.w = fmaxf(acc.w, fmaxf(v3f, 0.01f * v3f));
            }
            if (STORE) *(float4*)(g_cf1 + v * 128 + lane * 4) = acc;
            cmax.x = fmaxf(cmax.x, acc.x);
            cmax.y = fmaxf(cmax.y, acc.y);
            cmax.z = fmaxf(cmax.z, acc.z);
            cmax.w = fmaxf(cmax.w, acc.w);
        }
    }
    *(float4*)(sRed + warp * 128 + lane * 4) = cmax;
    __syncthreads();
    int t = threadIdx.x;
    if (t < 128) {
        float m = sRed[t];
#pragma unroll
        for (int r = 1; r < 16; r++) m = fmaxf(m, sRed[r * 128 + t]);
        atomicMax(&g_keys[slot * 128 + t], fkey(m));
    }
}

// ---------------- finalize: tiny GEMMs + group norm ----------------
__global__ void __launch_bounds__(384)
k_final(const float* __restrict__ second_b, const float* __restrict__ sgeo_b,
        const float* __restrict__ gnw, const float* __restrict__ gnb,
        float* __restrict__ out) {
    __shared__ float spf[384];
    __shared__ float spg[128];
    int t = threadIdx.x;
    if (t < 384) spf[t] = fdec(g_keys[t]);
    if (t < 128) spg[t] = leaky(fdec(g_keys[512 + t]));
    __syncthreads();
    if (t < 128) {
        float a = 0.f;
#pragma unroll 4
        for (int j = 0; j < 384; j++) a = fmaf(spf[j], g_W2T[j * 128 + t], a);
        a += second_b[t];
        out[t] = leaky(a);

        float g = 0.f;
#pragma unroll 4
        for (int j = 0; j < 128; j++) g = fmaf(spg[j], g_WgT[j * 128 + t], g);
        g += sgeo_b[t];

        float s = g;
        s += __shfl_xor_sync(0xffffffffu, s, 1, 8);
        s += __shfl_xor_sync(0xffffffffu, s, 2, 8);
        s += __shfl_xor_sync(0xffffffffu, s, 4, 8);
        float mu = s * 0.125f;
        float d = g - mu;
        float q = d * d;
        q += __shfl_xor_sync(0xffffffffu, q, 1, 8);
        q += __shfl_xor_sync(0xffffffffu, q, 2, 8);
        q += __shfl_xor_sync(0xffffffffu, q, 4, 8);
        float var = q * 0.125f;
        float xn = d * rsqrtf(var + 1e-5f);
        float y = xn * gnw[t] + gnb[t];
        float sgv = fdec(g_keys[384 + t]);
        float o = leaky(sgv) + y;
        out[128 + t] = leaky(o);
    }
}

// ---------------- host launcher ----------------
static cudaStream_t s_csr = 0, s_geo = 0;
static cudaEvent_t evFork = 0, evPrep = 0, evCsr = 0, evGeo = 0;

extern "C" void kernel_launch(void* const* d_in, const int* in_sizes, int n_in,
                              void* d_out, int out_size) {
    const float* child_feats = (const float*)d_in[0];
    const float* child_geo   = (const float*)d_in[1];
    const float* exists      = (const float*)d_in[2];
    const float* etype       = (const float*)d_in[3];
    const int*   eidx        = (const int*)d_in[4];
    const float* wop   = (const float*)d_in[5];
    const float* bop   = (const float*)d_in[6];
    const float* w2    = (const float*)d_in[7];
    const float* b2    = (const float*)d_in[8];
    const float* ew    = (const float*)d_in[9];
    const float* ebias = (const float*)d_in[10];
    const float* wgeo  = (const float*)d_in[11];
    const float* bgeo  = (const float*)d_in[12];
    const float* wg2   = (const float*)d_in[13];
    const float* bg2   = (const float*)d_in[14];
    const float* gnw   = (const float*)d_in[15];
    const float* gnb   = (const float*)d_in[16];
    const float* wskip = (const float*)d_in[17];
    const float* bskip = (const float*)d_in[18];
    float* out = (float*)d_out;

    (void)in_sizes; (void)n_in; (void)out_size;

    if (!s_csr) {
        cudaStreamCreateWithFlags(&s_csr, cudaStreamNonBlocking);
        cudaStreamCreateWithFlags(&s_geo, cudaStreamNonBlocking);
        cudaEventCreateWithFlags(&evFork, cudaEventDisableTiming);
        cudaEventCreateWithFlags(&evPrep, cudaEventDisableTiming);
        cudaEventCreateWithFlags(&evCsr,  cudaEventDisableTiming);
        cudaEventCreateWithFlags(&evGeo,  cudaEventDisableTiming);
    }

    // fork side streams from the capture-origin stream (required for graph capture)
    cudaEventRecord(evFork, 0);
    cudaStreamWaitEvent(s_csr, evFork, 0);
    cudaStreamWaitEvent(s_geo, evFork, 0);

    // CSR stream: independent of weight prep
    k_init<<<(N_NODES + 255) / 256, 256, 0, s_csr>>>();
    k_hist<<<(N_EDGES + 255) / 256, 256, 0, s_csr>>>(eidx);
    k_assign<<<(N_NODES + 255) / 256, 256, 0, s_csr>>>();
    k_sort<<<(N_EDGES + 255) / 256, 256, 0, s_csr>>>(eidx, etype);
    cudaEventRecord(evCsr, s_csr);

    // main stream: weight packing (incl. g_keys init)
    {
        const int total = 2 * 16384 + 11264 + 2 * 128 * 4
                        + 128 * 128 + 128 * 128 + 384 * 128 + 128 * 128 + 5 * 128;
        k_prep<<<(total + 255) / 256, 256>>>(wop, ew, wskip, wgeo, w2, wg2);
    }
    cudaEventRecord(evPrep, 0);

    // geo stream (needs packed weights + keys init)
    cudaStreamWaitEvent(s_geo, evPrep, 0);
    k_gemm<128, 128><<<(N_NODES + 127) / 128, 256, 0, s_geo>>>(
        child_geo, WS_SKIP, bskip, exists, 3);
    k_gemm<128, 128><<<(N_NODES + 127) / 128, 256, 0, s_geo>>>(
        child_geo, WS_GEO, bgeo, exists, 4);
    cudaEventRecord(evGeo, s_geo);

    // main chain: op GEMM on HMMA
    k_opgemm<<<(N_NODES + 127) / 128, 256>>>(child_feats, bop, exists);

    // iteration 0
    k_pgemm<<<(N_NODES + 63) / 64, 256>>>(0, 0);
    cudaStreamWaitEvent(0, evCsr, 0);
    k_edge<true><<<296, 512>>>(ebias, 0, 1);

    // iteration 1
    k_pgemm<<<(N_NODES + 63) / 64, 256>>>(1, 1);
    k_edge<false><<<296, 512>>>(ebias + 128, 1, 2);

    // finalize
    cudaStreamWaitEvent(0, evGeo, 0);
    k_final<<<1, 384>>>(b2, bg2, gnw, gnb, out);
}